// round 1
// baseline (speedup 1.0000x reference)
#include <cuda_runtime.h>
#include <math.h>

#define BB 16
#define TT 1024
#define HH 512
#define G4 2048
#define KK 512
#define NB 128

// ---------------- device-global scratch (no allocations allowed) ----------------
__device__ float g_gx[BB * TT * G4];   // 128 MB: per-layer input projection
__device__ float g_y [BB * TT * HH];   // 32 MB: layer-0 output sequence
__device__ float g_h [2][BB * HH];     // ping-pong hidden state
__device__ unsigned int g_bar_count;
__device__ unsigned int g_bar_gen;

// ---------------- grid-wide barrier (sense via monotonically increasing gen) ----
__device__ __forceinline__ void grid_barrier(unsigned nb)
{
    __syncthreads();
    if (threadIdx.x == 0) {
        __threadfence();
        volatile unsigned* vgen = (volatile unsigned*)&g_bar_gen;
        unsigned gen = *vgen;                       // read BEFORE arriving
        unsigned t = atomicAdd(&g_bar_count, 1u);
        if (t == nb - 1u) {
            atomicExch(&g_bar_count, 0u);
            __threadfence();
            atomicAdd(&g_bar_gen, 1u);              // release
        } else {
            while (*vgen == gen) { }                // spin on L2
        }
        __threadfence();                            // acquire
    }
    __syncthreads();
}

// ---------------- GEMM: g_gx[M][2048] = A[M][512] * W[2048][512]^T + b1 + b2 ----
__global__ __launch_bounds__(256, 2)
void gemm_bias_kernel(const float* __restrict__ Aext, int useY,
                      const float* __restrict__ W,
                      const float* __restrict__ b1,
                      const float* __restrict__ b2)
{
    const float* A = useY ? g_y : Aext;
    __shared__ float As[32][132];
    __shared__ float Bs[32][132];

    const int tid = threadIdx.x;
    const int bm = blockIdx.y * 128;
    const int bn = blockIdx.x * 128;
    const int tx = tid & 15;
    const int ty = tid >> 4;

    float acc[8][8];
#pragma unroll
    for (int i = 0; i < 8; i++)
#pragma unroll
        for (int j = 0; j < 8; j++) acc[i][j] = 0.f;

    for (int kc = 0; kc < KK; kc += 32) {
        __syncthreads();
#pragma unroll
        for (int p = 0; p < 4; p++) {
            int f = tid + 256 * p;
            int m = f >> 3, k4 = f & 7;
            float4 va = *(const float4*)&A[(size_t)(bm + m) * KK + kc + k4 * 4];
            As[k4*4+0][m] = va.x; As[k4*4+1][m] = va.y;
            As[k4*4+2][m] = va.z; As[k4*4+3][m] = va.w;
            float4 vb = *(const float4*)&W[(size_t)(bn + m) * KK + kc + k4 * 4];
            Bs[k4*4+0][m] = vb.x; Bs[k4*4+1][m] = vb.y;
            Bs[k4*4+2][m] = vb.z; Bs[k4*4+3][m] = vb.w;
        }
        __syncthreads();
#pragma unroll
        for (int kk = 0; kk < 32; kk++) {
            float a[8], b[8];
            *(float4*)&a[0] = *(float4*)&As[kk][ty * 4];
            *(float4*)&a[4] = *(float4*)&As[kk][64 + ty * 4];
            *(float4*)&b[0] = *(float4*)&Bs[kk][tx * 4];
            *(float4*)&b[4] = *(float4*)&Bs[kk][64 + tx * 4];
#pragma unroll
            for (int i = 0; i < 8; i++)
#pragma unroll
                for (int j = 0; j < 8; j++) acc[i][j] += a[i] * b[j];
        }
    }

    float bias[8];
#pragma unroll
    for (int j = 0; j < 8; j++) {
        int n = bn + (j < 4 ? tx * 4 + j : 64 + tx * 4 + (j - 4));
        bias[j] = b1[n] + b2[n];
    }
#pragma unroll
    for (int i = 0; i < 8; i++) {
        int m = bm + (i < 4 ? ty * 4 + i : 64 + ty * 4 + (i - 4));
        float* Crow = &g_gx[(size_t)m * G4 + bn];
        float4 v0 = { acc[i][0] + bias[0], acc[i][1] + bias[1],
                      acc[i][2] + bias[2], acc[i][3] + bias[3] };
        float4 v1 = { acc[i][4] + bias[4], acc[i][5] + bias[5],
                      acc[i][6] + bias[6], acc[i][7] + bias[7] };
        *(float4*)&Crow[tx * 4]      = v0;
        *(float4*)&Crow[64 + tx * 4] = v1;
    }
}

// ---------------- persistent LSTM scan -----------------------------------------
// 128 blocks x 256 threads. Block bid owns hidden cols [4*bid, 4*bid+4) for all
// 4 gates (16 rows of w_hh), weights register-resident for all 1024 steps.
// Thread (bq=tid&3, rq=(tid>>2)&3, kq=tid>>4): gate rq, batches 4bq..+3,
// k-slice kq*32..+31, 4 hidden cols -> 16 accumulators, 512 FMA/step.
__global__ __launch_bounds__(256, 1)
void lstm_scan_kernel(const float* __restrict__ w_hh,
                      const float* __restrict__ h0,
                      const float* __restrict__ c0,
                      float* __restrict__ hout,
                      int write_y)
{
    __shared__ float sh_h[16 * 546];     // h staged, conflict-free padding
    __shared__ float sh_part[8 * 258];   // kq partials
    __shared__ float sh_act[256];        // activated gates
    __shared__ float sh_c[64];           // cell state owned by this block

    const int tid = threadIdx.x;
    const int bid = blockIdx.x;
    const int bq = tid & 3;
    const int rq = (tid >> 2) & 3;       // gate index
    const int kq = tid >> 4;             // k-slice 0..15

    // preload w_hh slice into registers (lives across all 1024 steps)
    float wreg[4][32];
#pragma unroll
    for (int jj = 0; jj < 4; jj++) {
        const float* wr = &w_hh[(size_t)(rq * HH + bid * 4 + jj) * HH + kq * 32];
#pragma unroll
        for (int kk = 0; kk < 32; kk++) wreg[jj][kk] = wr[kk];
    }

    // init ping-pong h buffer 0 (each block copies its 64-float slice) and c
    if (tid < 64) {
        g_h[0][bid * 64 + tid] = h0[bid * 64 + tid];
        sh_c[tid] = c0[(tid >> 2) * HH + bid * 4 + (tid & 3)];
    }
    grid_barrier(NB);

    // this thread's reduction/activation output: (batch ob, gate og, col oj)
    const int ob = tid >> 4;
    const int ri = tid & 15;
    const int og = ri >> 2;
    const int oj = ri & 3;
    const size_t gx_base = (size_t)ob * TT * G4 + og * HH + bid * 4 + oj;

#pragma unroll 1
    for (int t = 0; t < TT; t++) {
        // prefetch streamed gx early (DRAM latency hidden under compute)
        float gxv = __ldg(&g_gx[gx_base + (size_t)t * G4]);

        const float* cur = g_h[t & 1];
        // stage h (32 KB, L2 broadcast; __ldcg avoids stale L1 across steps)
#pragma unroll
        for (int p = 0; p < 32; p++) {
            int i = tid + 256 * p;
            int b = i >> 9, k = i & 511;
            sh_h[b * 546 + (k >> 5) * 34 + (k & 31)] = __ldcg(&cur[i]);
        }
        __syncthreads();

        float acc[4][4];
#pragma unroll
        for (int jj = 0; jj < 4; jj++)
#pragma unroll
            for (int b2 = 0; b2 < 4; b2++) acc[jj][b2] = 0.f;

        const float* hb = &sh_h[kq * 34];
#pragma unroll
        for (int kk = 0; kk < 32; kk++) {
            float hv0 = hb[(4 * bq + 0) * 546 + kk];
            float hv1 = hb[(4 * bq + 1) * 546 + kk];
            float hv2 = hb[(4 * bq + 2) * 546 + kk];
            float hv3 = hb[(4 * bq + 3) * 546 + kk];
#pragma unroll
            for (int jj = 0; jj < 4; jj++) {
                float w = wreg[jj][kk];
                acc[jj][0] += w * hv0;
                acc[jj][1] += w * hv1;
                acc[jj][2] += w * hv2;
                acc[jj][3] += w * hv3;
            }
        }
        // fold kq pairs via shuffle (lane bit4 == kq bit0)
#pragma unroll
        for (int jj = 0; jj < 4; jj++)
#pragma unroll
            for (int b2 = 0; b2 < 4; b2++)
                acc[jj][b2] += __shfl_xor_sync(0xffffffffu, acc[jj][b2], 16);

        if ((tid & 16) == 0) {
            int w = tid >> 5;   // 0..7
#pragma unroll
            for (int jj = 0; jj < 4; jj++)
#pragma unroll
                for (int b2 = 0; b2 < 4; b2++) {
                    int out = (4 * bq + b2) * 16 + rq * 4 + jj;
                    sh_part[w * 258 + out] = acc[jj][b2];
                }
        }
        __syncthreads();

        // final reduction + bias'd gx + activation (one gate value per thread)
        float s = gxv;
#pragma unroll
        for (int p = 0; p < 8; p++) s += sh_part[p * 258 + tid];
        float v = (og == 2) ? tanhf(s) : 1.0f / (1.0f + expf(-s));
        sh_act[tid] = v;
        __syncthreads();

        if (tid < 64) {
            int b = tid >> 2, jj = tid & 3;
            float iv = sh_act[b * 16 + 0  + jj];
            float fv = sh_act[b * 16 + 4  + jj];
            float gv = sh_act[b * 16 + 8  + jj];
            float ov = sh_act[b * 16 + 12 + jj];
            float c = fv * sh_c[tid] + iv * gv;
            sh_c[tid] = c;
            float h = ov * tanhf(c);
            int jcol = bid * 4 + jj;
            g_h[(t + 1) & 1][b * HH + jcol] = h;
            if (write_y) g_y[((size_t)b * TT + t) * HH + jcol] = h;
            if (t == TT - 1) hout[b * HH + jcol] = h;
        }
        grid_barrier(NB);
    }
}

// ---------------- launch ---------------------------------------------------------
extern "C" void kernel_launch(void* const* d_in, const int* in_sizes, int n_in,
                              void* d_out, int out_size)
{
    const float* x     = (const float*)d_in[0];
    const float* h0    = (const float*)d_in[1];
    const float* c0    = (const float*)d_in[2];
    const float* w_ih0 = (const float*)d_in[3];
    const float* w_hh0 = (const float*)d_in[4];
    const float* b_ih0 = (const float*)d_in[5];
    const float* b_hh0 = (const float*)d_in[6];
    const float* w_ih1 = (const float*)d_in[7];
    const float* w_hh1 = (const float*)d_in[8];
    const float* b_ih1 = (const float*)d_in[9];
    const float* b_hh1 = (const float*)d_in[10];
    float* out = (float*)d_out;

    dim3 ggrid(G4 / 128, (BB * TT) / 128);   // (16, 128)

    // layer 0
    gemm_bias_kernel<<<ggrid, 256>>>(x, 0, w_ih0, b_ih0, b_hh0);
    lstm_scan_kernel<<<NB, 256>>>(w_hh0, h0, c0, out, 1);
    // layer 1 (input = layer-0 output sequence g_y)
    gemm_bias_kernel<<<ggrid, 256>>>(nullptr, 1, w_ih1, b_ih1, b_hh1);
    lstm_scan_kernel<<<NB, 256>>>(w_hh1, h0 + BB * HH, c0 + BB * HH, out + BB * HH, 0);
}